// round 6
// baseline (speedup 1.0000x reference)
#include <cuda_runtime.h>

// ---------------------------------------------------------------------------
// PCritical step, B=32, N=4096 — fused single pass over W, sparse-spike GEMMs.
// Outputs concatenated float32 in reference return order:
//   S (B,N) | mem_pot_n (B,N) | W_new (N,N) | mem_cur_n (B,N) |
//   mem_pot_p_n (B,N) | mem_cur_p_n (B,N) | refrac_new (B,N)
// ---------------------------------------------------------------------------

#define Bsz 32
#define Nsz 4096
#define BN  (Bsz * Nsz)        // 131072
#define NN  (Nsz * Nsz)        // 16777216

#define C_ALPHA 0.025f
#define C_BETA  0.00025f
#define C_TNOW  10.0f
#define C_INV_TAU_V 0.9801986733067553f
#define C_INV_TAU_I 0.36787944117144233f

#define OUT_S    ((long long)0)
#define OUT_POT  ((long long)BN)
#define OUT_W    ((long long)(2LL * BN))
#define OUT_CUR  ((long long)(2LL * BN + NN))
#define OUT_POTP ((long long)(3LL * BN + NN))
#define OUT_CURP ((long long)(4LL * BN + NN))
#define OUT_REFR ((long long)(5LL * BN + NN))

#define ICHUNKS 32             // 4096 / 128  (grid.y)
#define JCHUNKS 32             // 4096 / 128  (grid.x)
#define PITCH   129            // 129 ≡ 1 (mod 32): rows AND columns conflict-free

// scratch (no dynamic allocation allowed)
__device__ __align__(16) unsigned g_masks[Nsz];          // bit b <=> S[b,n]==1
__device__ __align__(16) float    g_e[Nsz];              // exp(max_st/50)
__device__ __align__(16) float    g_ie[Nsz];             // exp(-max_st/50)
__device__ __align__(16) float    g_A[Nsz];              // sp ? ALPHA*e  : 0
__device__ __align__(16) float    g_Ai[Nsz];             // sp ? ALPHA*ie : 0
__device__ __align__(16) float    g_accP[ICHUNKS * BN];  // partials S@W_new
__device__ __align__(16) float    g_accTP[JCHUNKS * BN]; // partials S@W_new^T

// ---------------------------------------------------------------------------
// K1: per-neuron reductions over the batch + exp precompute.
// 2-way batch split per neuron (lanes 2t/2t+1 share a neuron, each scans 16
// batch rows), merged with shfl — doubles MLP of this latency-bound scan.
// ---------------------------------------------------------------------------
__global__ void __launch_bounds__(128) k_prologue(
    const float* __restrict__ mem_pot,
    const float* __restrict__ mem_pot_paired,
    const float* __restrict__ st)
{
    int gid  = blockIdx.x * 128 + threadIdx.x;   // 8192 threads
    int n    = gid >> 1;
    int half = gid & 1;
    int b0   = half * 16;

    unsigned mp_ = 0u;
    bool anyp = false;
#pragma unroll
    for (int k = 0; k < 16; ++k) {
        int b = b0 + k;
        float mp = mem_pot[b * Nsz + n];
        if (mp > 1.0f) mp_ |= (1u << b);
        float mpp = mem_pot_paired[b * Nsz + n];
        if (((mpp - 1.0f) - C_ALPHA) > 0.0f) anyp = true;
    }
    unsigned m = mp_ | __shfl_xor_sync(0xffffffffu, mp_, 1);
    anyp = anyp | (bool)__shfl_xor_sync(0xffffffffu, (int)anyp, 1);

    if (half == 0) {
        float stn = st[n];
        float maxst = (m == 0xffffffffu) ? C_TNOW
                    : (m ? fmaxf(C_TNOW, stn) : stn);
        float e  = expf(maxst * (1.0f / 50.0f));
        float ie = expf(-maxst * (1.0f / 50.0f));
        g_masks[n] = m;
        g_e[n]  = e;
        g_ie[n] = ie;
        g_A[n]  = anyp ? C_ALPHA * e  : 0.0f;
        g_Ai[n] = anyp ? C_ALPHA * ie : 0.0f;
    }
}

__device__ __forceinline__ float upd1(float w, float A, float Ai, float e, float ie)
{
    float sub = fmaxf(A * ie, Ai * e);        // 0 when row not paired-spiking
    float u = (w + C_BETA) - sub;
    u = fminf(fmaxf(u, 0.0f), 1.0f);
    return (w > 0.0f) ? u : w;                // sign_mask = W_rec > 0
}

// ---------------------------------------------------------------------------
// K2 (fused): W update + both binary-S GEMMs; spike-sparse ffs loops.
// 256 threads, 3 blocks/SM, tile 128 i x 128 j, 1024 blocks.
//   Phase A: coalesced update, tile -> smem c[128][129]
//   Phase B: each warp: 4 batches, acc[b][j]  over active rows (ffs loop)
//   Phase C: each warp: 4 batches, accT[b][i] over active cols (ffs loop)
// Lanes carry the output dim -> every LDS is a full 128B wavefront,
// conflict-free in both row and column direction (PITCH=129).
// ---------------------------------------------------------------------------
__global__ void __launch_bounds__(256, 3) k_fused(
    const float* __restrict__ W, float* __restrict__ Wout)
{
    extern __shared__ float sm[];
    float*    c   = sm;                                  // [128][129]
    unsigned* rbj = (unsigned*)(sm + 128 * PITCH);       // [32][4] col words
    unsigned* rbi = rbj + 128;                           // [32][4] row words

    const int jc   = blockIdx.x;       // 0..31
    const int ic   = blockIdx.y;       // 0..31
    const int tid  = threadIdx.x;
    const int warp = tid >> 5;         // 0..7
    const int lane = tid & 31;
    const int jg0  = jc * 128;
    const int ig0  = ic * 128;

    // per-column exp factors (block-constant)
    float e0  = g_e[jg0 + lane];       float ie0 = g_ie[jg0 + lane];
    float e1  = g_e[jg0 + lane + 32];  float ie1 = g_ie[jg0 + lane + 32];
    float e2  = g_e[jg0 + lane + 64];  float ie2 = g_ie[jg0 + lane + 64];
    float e3  = g_e[jg0 + lane + 96];  float ie3 = g_ie[jg0 + lane + 96];

    // transposed masks: warps 0-3 -> columns, warps 4-7 -> rows
    if (warp < 4) {
        unsigned mw = g_masks[jg0 + warp * 32 + lane];
#pragma unroll
        for (int b = 0; b < 32; ++b) {
            unsigned w = __ballot_sync(0xffffffffu, (mw >> b) & 1u);
            if (lane == b) rbj[b * 4 + warp] = w;
        }
    } else {
        int q = warp - 4;
        unsigned mw = g_masks[ig0 + q * 32 + lane];
#pragma unroll
        for (int b = 0; b < 32; ++b) {
            unsigned w = __ballot_sync(0xffffffffu, (mw >> b) & 1u);
            if (lane == b) rbi[b * 4 + q] = w;
        }
    }

    // ---- Phase A: update 16 rows per warp ----
#pragma unroll 4
    for (int r = 0; r < 16; ++r) {
        int il = warp * 16 + r;
        int ig = ig0 + il;
        float A  = g_A[ig];
        float Ai = g_Ai[ig];
        const float* wr = W    + (size_t)ig * Nsz + jg0;
        float*       wo = Wout + (size_t)ig * Nsz + jg0;
        float w0 = wr[lane];
        float w1 = wr[lane + 32];
        float w2 = wr[lane + 64];
        float w3 = wr[lane + 96];
        float u0 = upd1(w0, A, Ai, e0, ie0);
        float u1 = upd1(w1, A, Ai, e1, ie1);
        float u2 = upd1(w2, A, Ai, e2, ie2);
        float u3 = upd1(w3, A, Ai, e3, ie3);
        wo[lane]      = u0;
        wo[lane + 32] = u1;
        wo[lane + 64] = u2;
        wo[lane + 96] = u3;
        float* cr = c + il * PITCH;
        cr[lane]      = u0;
        cr[lane + 32] = u1;
        cr[lane + 64] = u2;
        cr[lane + 96] = u3;
    }
    __syncthreads();

    // ---- Phase B: acc[b][j] over active rows; 4 batches per warp ----
#pragma unroll
    for (int k = 0; k < 4; ++k) {
        int b = warp * 4 + k;
        float a0 = 0, a1 = 0, a2 = 0, a3 = 0;
#pragma unroll
        for (int q = 0; q < 4; ++q) {
            unsigned m = rbi[b * 4 + q];
            while (m) {
                int r = q * 32 + __ffs(m) - 1; m &= m - 1;
                const float* cr = c + r * PITCH;
                a0 += cr[lane];
                a1 += cr[lane + 32];
                a2 += cr[lane + 64];
                a3 += cr[lane + 96];
            }
        }
        size_t o = ((size_t)ic * Bsz + b) * Nsz + jg0 + lane;
        g_accP[o]      = a0;
        g_accP[o + 32] = a1;
        g_accP[o + 64] = a2;
        g_accP[o + 96] = a3;
    }

    // ---- Phase C: accT[b][i] over active cols; 4 batches per warp ----
    const int lp = lane * PITCH;
#pragma unroll
    for (int k = 0; k < 4; ++k) {
        int b = warp * 4 + k;
        float a0 = 0, a1 = 0, a2 = 0, a3 = 0;
#pragma unroll
        for (int q = 0; q < 4; ++q) {
            unsigned m = rbj[b * 4 + q];
            while (m) {
                int j = q * 32 + __ffs(m) - 1; m &= m - 1;
                const float* cc = c + j + lp;
                a0 += cc[0];
                a1 += cc[32 * PITCH];
                a2 += cc[64 * PITCH];
                a3 += cc[96 * PITCH];
            }
        }
        size_t o = ((size_t)jc * Bsz + b) * Nsz + ig0 + lane;
        g_accTP[o]      = a0;
        g_accTP[o + 32] = a1;
        g_accTP[o + 64] = a2;
        g_accTP[o + 96] = a3;
    }
}

// ---------------------------------------------------------------------------
// K3: epilogue — reduce partials, integrate, leak, reset, refractory
// ---------------------------------------------------------------------------
__global__ void __launch_bounds__(256) k_epilogue(
    const float* __restrict__ inp,
    const float* __restrict__ mem_pot,
    const float* __restrict__ mem_cur,
    const float* __restrict__ mem_pot_paired,
    const float* __restrict__ mem_cur_paired,
    const int*   __restrict__ refrac,
    float* __restrict__ out)
{
    int t = blockIdx.x * 256 + threadIdx.x;   // BN threads
    int b = t >> 12;
    int n = t & (Nsz - 1);

    float acc = 0.0f;
#pragma unroll
    for (int cN = 0; cN < ICHUNKS; ++cN) acc += g_accP[(size_t)cN * BN + t];
    float accT = 0.0f;
#pragma unroll
    for (int cN = 0; cN < JCHUNKS; ++cN) accT += g_accTP[(size_t)cN * BN + t];

    int r  = refrac[t];
    int rd = (r > 0) ? (r - 1) : r;
    bool active = (rd == 0);

    unsigned m = g_masks[n];
    bool s  = ((m >> b) & 1u) != 0u;
    float mppv = mem_pot_paired[t];
    bool sp = ((mppv - 1.0f) - C_ALPHA) > 0.0f;

    float mp   = mem_pot[t];
    float mc   = mem_cur[t];
    float mcpv = mem_cur_paired[t];

    float mcn  = active ? (inp[t] + acc) + mc : mc;
    float mcpn = active ? accT + mcpv : mcpv;
    float mpn  = active ? mcn + mp : mp;
    float mppn = active ? mcpn + mppv : mppv;

    mpn  *= C_INV_TAU_V;
    mcn  *= C_INV_TAU_I;
    mppn *= C_INV_TAU_V;
    mcpn *= C_INV_TAU_I;

    if (s)  mpn  = 0.0f;
    if (sp) mppn = 0.0f;
    float rn = s ? 2.0f : (float)rd;

    out[OUT_S    + t] = s ? 1.0f : 0.0f;
    out[OUT_POT  + t] = mpn;
    out[OUT_CUR  + t] = mcn;
    out[OUT_POTP + t] = mppn;
    out[OUT_CURP + t] = mcpn;
    out[OUT_REFR + t] = rn;
}

// ---------------------------------------------------------------------------
extern "C" void kernel_launch(void* const* d_in, const int* in_sizes, int n_in,
                              void* d_out, int out_size)
{
    const float* inp      = (const float*)d_in[0];
    const float* W_rec    = (const float*)d_in[1];
    const float* mem_pot  = (const float*)d_in[2];
    const float* mem_cur  = (const float*)d_in[3];
    const float* mpp      = (const float*)d_in[4];
    const float* mcp      = (const float*)d_in[5];
    const float* st       = (const float*)d_in[6];
    const int*   refrac   = (const int*)d_in[7];
    float* out = (float*)d_out;
    float* Wout = out + OUT_W;

    const int smem_bytes = (128 * PITCH + 256) * 4;   // ~67 KB -> 3 blocks/SM
    cudaFuncSetAttribute(k_fused, cudaFuncAttributeMaxDynamicSharedMemorySize,
                         smem_bytes);

    k_prologue<<<2 * Nsz / 128, 128>>>(mem_pot, mpp, st);
    k_fused<<<dim3(JCHUNKS, ICHUNKS), 256, smem_bytes>>>(W_rec, Wout);
    k_epilogue<<<BN / 256, 256>>>(inp, mem_pot, mem_cur, mpp, mcp, refrac, out);
}